// round 6
// baseline (speedup 1.0000x reference)
#include <cuda_runtime.h>
#include <cuda_bf16.h>
#include <mma.h>

using namespace nvcuda;

static constexpr int NN = 768;
static constexpr size_t NTOK = (size_t)NN * NN;  // 589824

__device__ __align__(256) __nv_bfloat16 g_leftT[128 * 589824];   // [h][tok]
__device__ __align__(256) __nv_bfloat16 g_rightT[128 * 589824];  // [h][tok]
__device__ __align__(256) float         g_gate[589824 * 128];    // [tok][h]
__device__ __align__(256) __nv_bfloat16 g_outT[128 * 589824];    // [d][i*768+j]

#define LDX 136

// -------- Stage A: LN + 5 projections (bf16x3), gating, transposed stores ----
__global__ __launch_bounds__(256) void kA(
    const float* __restrict__ x, const float* __restrict__ mask,
    const float* __restrict__ nw_, const float* __restrict__ nb_,
    const float* __restrict__ wl, const float* __restrict__ wr,
    const float* __restrict__ wlg, const float* __restrict__ wrg,
    const float* __restrict__ wog)
{
    extern __shared__ __align__(16) char smraw[];
    __nv_bfloat16* xh  = (__nv_bfloat16*)smraw;
    __nv_bfloat16* xl  = xh  + 128 * LDX;
    __nv_bfloat16* wPh = xl  + 128 * LDX;
    __nv_bfloat16* wPl = wPh + 128 * LDX;
    __nv_bfloat16* wGh = wPl + 128 * LDX;
    __nv_bfloat16* wGl = wGh + 128 * LDX;
    float* stage = (float*)(wGl + 128 * LDX);   // 128 x 36
    float* msk   = stage + 128 * 36;            // 128

    const int tid = threadIdx.x, w = tid >> 5, lane = tid & 31;
    const size_t t0 = (size_t)blockIdx.x * 128;

    float4 nw4 = *(const float4*)&nw_[lane * 4];
    float4 nb4 = *(const float4*)&nb_[lane * 4];
    for (int m = w; m < 128; m += 8) {
        float4 v = *(const float4*)&x[(t0 + m) * 128 + lane * 4];
        float s = v.x + v.y + v.z + v.w;
        float q = v.x*v.x + v.y*v.y + v.z*v.z + v.w*v.w;
        #pragma unroll
        for (int o = 16; o; o >>= 1) {
            s += __shfl_xor_sync(~0u, s, o);
            q += __shfl_xor_sync(~0u, q, o);
        }
        float mu = s * (1.f/128.f);
        float rs = rsqrtf(q * (1.f/128.f) - mu*mu + 1e-5f);
        float y[4] = { (v.x-mu)*rs*nw4.x + nb4.x, (v.y-mu)*rs*nw4.y + nb4.y,
                       (v.z-mu)*rs*nw4.z + nb4.z, (v.w-mu)*rs*nw4.w + nb4.w };
        int base = m * LDX + lane * 4;
        #pragma unroll
        for (int c = 0; c < 4; c++) {
            __nv_bfloat16 h = __float2bfloat16(y[c]);
            xh[base + c] = h;
            xl[base + c] = __float2bfloat16(y[c] - __bfloat162float(h));
        }
    }
    if (tid < 128) msk[tid] = mask[t0 + tid];

    const float* WPs[3] = { wl, wr, wog };
    const float* WGs[3] = { wlg, wrg, nullptr };
    const int mw = w & 3, nwp = w >> 2, m0 = mw * 32;

    for (int p = 0; p < 3; p++) {
        __syncthreads();
        const float* WP = WPs[p];
        const float* WG = WGs[p];
        for (int idx = tid; idx < 128 * 128; idx += 256) {
            int n = idx >> 7, k = idx & 127;
            float wv = WP[idx];
            __nv_bfloat16 h = __float2bfloat16(wv);
            wPh[n * LDX + k] = h;
            wPl[n * LDX + k] = __float2bfloat16(wv - __bfloat162float(h));
            if (p < 2) {
                float gv = WG[idx];
                __nv_bfloat16 gh = __float2bfloat16(gv);
                wGh[n * LDX + k] = gh;
                wGl[n * LDX + k] = __float2bfloat16(gv - __bfloat162float(gh));
            }
        }
        __syncthreads();

        for (int nh = 0; nh < 2; nh++) {
            const int nb0 = nwp * 64 + nh * 32;
            wmma::fragment<wmma::accumulator,16,16,16,float> accP[2][2], accG[2][2];
            #pragma unroll
            for (int im = 0; im < 2; im++)
                #pragma unroll
                for (int in = 0; in < 2; in++) {
                    wmma::fill_fragment(accP[im][in], 0.f);
                    wmma::fill_fragment(accG[im][in], 0.f);
                }
            for (int k0 = 0; k0 < 128; k0 += 16) {
                wmma::fragment<wmma::matrix_a,16,16,16,__nv_bfloat16,wmma::row_major> ah[2], al[2];
                wmma::fragment<wmma::matrix_b,16,16,16,__nv_bfloat16,wmma::col_major> bh[2], bl[2], gh[2], gl[2];
                #pragma unroll
                for (int im = 0; im < 2; im++) {
                    wmma::load_matrix_sync(ah[im], xh + (m0+im*16)*LDX + k0, LDX);
                    wmma::load_matrix_sync(al[im], xl + (m0+im*16)*LDX + k0, LDX);
                }
                #pragma unroll
                for (int in = 0; in < 2; in++) {
                    wmma::load_matrix_sync(bh[in], wPh + (nb0+in*16)*LDX + k0, LDX);
                    wmma::load_matrix_sync(bl[in], wPl + (nb0+in*16)*LDX + k0, LDX);
                    if (p < 2) {
                        wmma::load_matrix_sync(gh[in], wGh + (nb0+in*16)*LDX + k0, LDX);
                        wmma::load_matrix_sync(gl[in], wGl + (nb0+in*16)*LDX + k0, LDX);
                    }
                }
                #pragma unroll
                for (int im = 0; im < 2; im++)
                    #pragma unroll
                    for (int in = 0; in < 2; in++) {
                        wmma::mma_sync(accP[im][in], al[im], bh[in], accP[im][in]);
                        wmma::mma_sync(accP[im][in], ah[im], bl[in], accP[im][in]);
                        wmma::mma_sync(accP[im][in], ah[im], bh[in], accP[im][in]);
                        if (p < 2) {
                            wmma::mma_sync(accG[im][in], al[im], gh[in], accG[im][in]);
                            wmma::mma_sync(accG[im][in], ah[im], gl[in], accG[im][in]);
                            wmma::mma_sync(accG[im][in], ah[im], gh[in], accG[im][in]);
                        }
                    }
            }

            if (p < 2) {
                #pragma unroll
                for (int im = 0; im < 2; im++)
                    #pragma unroll
                    for (int in = 0; in < 2; in++)
                        #pragma unroll
                        for (int t = 0; t < 8; t++)
                            accP[im][in].x[t] *= 1.f / (1.f + expf(-accG[im][in].x[t]));
                __nv_bfloat16* dst = (p == 0) ? g_leftT : g_rightT;
                for (int g = 0; g < 2; g++) {
                    __syncthreads();
                    if (nwp == g) {
                        #pragma unroll
                        for (int im = 0; im < 2; im++)
                            #pragma unroll
                            for (int in = 0; in < 2; in++)
                                wmma::store_matrix_sync(stage + (m0+im*16)*36 + in*16,
                                                        accP[im][in], 36, wmma::mem_row_major);
                    }
                    __syncthreads();
                    const int h0 = g * 64 + nh * 32;
                    for (int e = tid; e < 128 * 32; e += 256) {
                        int m = e & 127, n = e >> 7;
                        dst[(size_t)(h0 + n) * NTOK + t0 + m] =
                            __float2bfloat16(stage[m * 36 + n] * msk[m]);
                    }
                }
            } else {
                #pragma unroll
                for (int im = 0; im < 2; im++)
                    #pragma unroll
                    for (int in = 0; in < 2; in++) {
                        #pragma unroll
                        for (int t = 0; t < 8; t++)
                            accP[im][in].x[t] = 1.f / (1.f + expf(-accP[im][in].x[t]));
                        wmma::store_matrix_sync(
                            g_gate + (t0 + m0 + im*16) * 128 + nb0 + in*16,
                            accP[im][in], 128, wmma::mem_row_major);
                    }
            }
        }
    }
}

// -------- Stage B: per-channel 768x768x768 bf16 GEMM, out rounded to bf16 ----
__global__ __launch_bounds__(256) void kB(void)
{
    __shared__ __align__(16) char sbuf[34816];
    __nv_bfloat16* sA = (__nv_bfloat16*)sbuf;   // 128 x 40
    __nv_bfloat16* sB = sA + 128 * 40;          // 128 x 40
    float* stg = (float*)sbuf;                  // epilogue: 8 x (16 x 68)

    const int tid = threadIdx.x, w = tid >> 5, lane = tid & 31;
    const int d = blockIdx.y, ti = blockIdx.x % 6, tj = blockIdx.x / 6;
    const __nv_bfloat16* Lb = g_leftT  + (size_t)d * NTOK + (size_t)ti * 128 * NN;
    const __nv_bfloat16* Rb = g_rightT + (size_t)d * NTOK + (size_t)tj * 128 * NN;
    __nv_bfloat16* Ob = g_outT + (size_t)d * NTOK + (size_t)ti * 128 * NN + tj * 128;

    const int mw = w & 3, nw = w >> 2;
    wmma::fragment<wmma::accumulator,16,16,16,float> acc[2][4];
    #pragma unroll
    for (int im = 0; im < 2; im++)
        #pragma unroll
        for (int in = 0; in < 4; in++) wmma::fill_fragment(acc[im][in], 0.f);

    for (int k0 = 0; k0 < NN; k0 += 32) {
        __syncthreads();
        for (int idx = tid; idx < 512; idx += 256) {
            int r = idx >> 2, c = idx & 3;
            *(uint4*)&sA[r*40 + c*8] = *(const uint4*)&Lb[r*NN + k0 + c*8];
            *(uint4*)&sB[r*40 + c*8] = *(const uint4*)&Rb[r*NN + k0 + c*8];
        }
        __syncthreads();
        #pragma unroll
        for (int ks = 0; ks < 32; ks += 16) {
            wmma::fragment<wmma::matrix_a,16,16,16,__nv_bfloat16,wmma::row_major> a[2];
            wmma::fragment<wmma::matrix_b,16,16,16,__nv_bfloat16,wmma::col_major> b[4];
            #pragma unroll
            for (int im = 0; im < 2; im++)
                wmma::load_matrix_sync(a[im], sA + (mw*32+im*16)*40 + ks, 40);
            #pragma unroll
            for (int in = 0; in < 4; in++)
                wmma::load_matrix_sync(b[in], sB + (nw*64+in*16)*40 + ks, 40);
            #pragma unroll
            for (int im = 0; im < 2; im++)
                #pragma unroll
                for (int in = 0; in < 4; in++)
                    wmma::mma_sync(acc[im][in], a[im], b[in], acc[im][in]);
        }
    }

    __syncthreads();
    float* ws = stg + w * (16 * 68);
    #pragma unroll
    for (int im = 0; im < 2; im++) {
        #pragma unroll
        for (int in = 0; in < 4; in++)
            wmma::store_matrix_sync(ws + in*16, acc[im][in], 68, wmma::mem_row_major);
        __syncwarp();
        int rbase = mw * 32 + im * 16;
        for (int e = lane; e < 16 * 64; e += 32) {
            int r = e >> 6, n = e & 63;
            Ob[(size_t)(rbase + r) * NN + nw*64 + n] = __float2bfloat16(ws[r*68 + n]);
        }
        __syncwarp();
    }
}

// -------- Stage C: channel LN + gate + final projection (bf16x3) ------------
__global__ __launch_bounds__(256) void kC(
    const float* __restrict__ onw, const float* __restrict__ onb,
    const float* __restrict__ wout, float* __restrict__ out)
{
    extern __shared__ __align__(16) char smraw[];
    float* s = (float*)smraw;                         // 128 x 132
    __nv_bfloat16* yh = (__nv_bfloat16*)(s + 128*132);
    __nv_bfloat16* yl = yh + 128 * LDX;
    __nv_bfloat16* wh = yl + 128 * LDX;
    __nv_bfloat16* wl = wh + 128 * LDX;

    const int tid = threadIdx.x, w = tid >> 5, lane = tid & 31;
    const size_t t0 = (size_t)blockIdx.x * 128;

    for (int idx = tid; idx < 128 * 128; idx += 256) {
        float wv = wout[idx];
        __nv_bfloat16 h = __float2bfloat16(wv);
        int n = idx >> 7, k = idx & 127;
        wh[n * LDX + k] = h;
        wl[n * LDX + k] = __float2bfloat16(wv - __bfloat162float(h));
    }
    for (int idx = tid; idx < 128 * 128; idx += 256) {
        int dch = idx >> 7, m = idx & 127;
        s[m * 132 + dch] = __bfloat162float(g_outT[(size_t)dch * NTOK + t0 + m]);
    }
    __syncthreads();

    float4 w4 = *(const float4*)&onw[lane * 4];
    float4 b4 = *(const float4*)&onb[lane * 4];
    for (int m = w; m < 128; m += 8) {
        float4 v = *(const float4*)&s[m * 132 + lane * 4];
        float ssum = v.x + v.y + v.z + v.w;
        float q = v.x*v.x + v.y*v.y + v.z*v.z + v.w*v.w;
        #pragma unroll
        for (int o = 16; o; o >>= 1) {
            ssum += __shfl_xor_sync(~0u, ssum, o);
            q += __shfl_xor_sync(~0u, q, o);
        }
        float mu = ssum * (1.f/128.f);
        float rs = rsqrtf(q * (1.f/128.f) - mu*mu + 1e-5f);
        float4 g = *(const float4*)&g_gate[(t0 + m) * 128 + lane * 4];
        float* row = &s[m * 132 + lane * 4];
        row[0] = ((v.x-mu)*rs*w4.x + b4.x) * g.x;
        row[1] = ((v.y-mu)*rs*w4.y + b4.y) * g.y;
        row[2] = ((v.z-mu)*rs*w4.z + b4.z) * g.z;
        row[3] = ((v.w-mu)*rs*w4.w + b4.w) * g.w;
    }
    __syncthreads();

    for (int idx = tid; idx < 128 * 128; idx += 256) {
        int m = idx >> 7, h = idx & 127;
        float v = s[m * 132 + h];
        __nv_bfloat16 hv = __float2bfloat16(v);
        yh[m * LDX + h] = hv;
        yl[m * LDX + h] = __float2bfloat16(v - __bfloat162float(hv));
    }
    __syncthreads();

    const int mw = w & 3, nw2 = w >> 2, m0 = mw * 32, n0 = nw2 * 64;
    wmma::fragment<wmma::accumulator,16,16,16,float> acc[2][4];
    #pragma unroll
    for (int im = 0; im < 2; im++)
        #pragma unroll
        for (int in = 0; in < 4; in++) wmma::fill_fragment(acc[im][in], 0.f);

    for (int k0 = 0; k0 < 128; k0 += 16) {
        wmma::fragment<wmma::matrix_a,16,16,16,__nv_bfloat16,wmma::row_major> ah[2], al[2];
        wmma::fragment<wmma::matrix_b,16,16,16,__nv_bfloat16,wmma::col_major> bh[4], bl[4];
        #pragma unroll
        for (int im = 0; im < 2; im++) {
            wmma::load_matrix_sync(ah[im], yh + (m0+im*16)*LDX + k0, LDX);
            wmma::load_matrix_sync(al[im], yl + (m0+im*16)*LDX + k0, LDX);
        }
        #pragma unroll
        for (int in = 0; in < 4; in++) {
            wmma::load_matrix_sync(bh[in], wh + (n0+in*16)*LDX + k0, LDX);
            wmma::load_matrix_sync(bl[in], wl + (n0+in*16)*LDX + k0, LDX);
        }
        #pragma unroll
        for (int im = 0; im < 2; im++)
            #pragma unroll
            for (int in = 0; in < 4; in++) {
                wmma::mma_sync(acc[im][in], al[im], bh[in], acc[im][in]);
                wmma::mma_sync(acc[im][in], ah[im], bl[in], acc[im][in]);
                wmma::mma_sync(acc[im][in], ah[im], bh[in], acc[im][in]);
            }
    }
    #pragma unroll
    for (int im = 0; im < 2; im++)
        #pragma unroll
        for (int in = 0; in < 4; in++)
            wmma::store_matrix_sync(out + (t0 + m0 + im*16) * 128 + n0 + in*16,
                                    acc[im][in], 128, wmma::mem_row_major);
}

extern "C" void kernel_launch(void* const* d_in, const int* in_sizes, int n_in,
                              void* d_out, int out_size) {
    const float* x    = (const float*)d_in[0];
    const float* mask = (const float*)d_in[1];
    const float* nw   = (const float*)d_in[2];
    const float* nb   = (const float*)d_in[3];
    const float* wlft = (const float*)d_in[4];
    const float* wrgt = (const float*)d_in[5];
    const float* wlg  = (const float*)d_in[6];
    const float* wrg  = (const float*)d_in[7];
    const float* wog  = (const float*)d_in[8];
    const float* onw  = (const float*)d_in[9];
    const float* onb  = (const float*)d_in[10];
    const float* wout = (const float*)d_in[11];
    float* out = (float*)d_out;

    size_t smA = 6 * 128 * LDX * sizeof(__nv_bfloat16) + (128*36 + 128) * sizeof(float);
    size_t smC = 128 * 132 * sizeof(float) + 4 * 128 * LDX * sizeof(__nv_bfloat16);
    cudaFuncSetAttribute(kA, cudaFuncAttributeMaxDynamicSharedMemorySize, (int)smA);
    cudaFuncSetAttribute(kC, cudaFuncAttributeMaxDynamicSharedMemorySize, (int)smC);

    kA<<<4608, 256, smA>>>(x, mask, nw, nb, wlft, wrgt, wlg, wrg, wog);
    kB<<<dim3(36, 128), 256>>>();
    kC<<<4608, 256, smC>>>(onw, onb, wout, out);
}

// round 9
// speedup vs baseline: 2.1620x; 2.1620x over previous
#include <cuda_runtime.h>
#include <cuda_bf16.h>
#include <mma.h>
#include <cstdint>

using namespace nvcuda;

static constexpr int NN = 768;
static constexpr size_t NTOK = (size_t)NN * NN;  // 589824

__device__ __align__(256) __nv_bfloat16 g_leftT[128 * 589824];   // [h][tok]
__device__ __align__(256) __nv_bfloat16 g_rightT[128 * 589824];  // [h][tok]
__device__ __align__(256) float         g_gate[589824 * 128];    // [tok][h]
__device__ __align__(256) __nv_bfloat16 g_outT[128 * 589824];    // [d][i*768+j]

#define LDX 136
// pre-split weights: 0=wl 1=wr 2=wlg 3=wrg 4=wog 5=wout
__device__ __align__(256) __nv_bfloat16 g_wsh[6][128 * LDX];
__device__ __align__(256) __nv_bfloat16 g_wsl[6][128 * LDX];

__device__ __forceinline__ float fsig(float z) { return 1.f / (1.f + __expf(-z)); }

__device__ __forceinline__ void cp16(void* smem, const void* g) {
    unsigned int s = (unsigned int)__cvta_generic_to_shared(smem);
    asm volatile("cp.async.cg.shared.global [%0], [%1], 16;\n" :: "r"(s), "l"(g));
}
#define CP_COMMIT() asm volatile("cp.async.commit_group;\n")
#define CP_WAIT(n)  asm volatile("cp.async.wait_group %0;\n" :: "n"(n))

// -------- Stage W: split 6 weight matrices into bf16 hi/lo ------------------
__global__ __launch_bounds__(256) void kW(
    const float* __restrict__ wl, const float* __restrict__ wr,
    const float* __restrict__ wlg, const float* __restrict__ wrg,
    const float* __restrict__ wog, const float* __restrict__ wout)
{
    const float* Ws[6] = { wl, wr, wlg, wrg, wog, wout };
    const float* W = Ws[blockIdx.x];
    for (int idx = threadIdx.x; idx < 128 * 128; idx += 256) {
        int n = idx >> 7, k = idx & 127;
        float v = W[idx];
        __nv_bfloat16 h = __float2bfloat16(v);
        g_wsh[blockIdx.x][n * LDX + k] = h;
        g_wsl[blockIdx.x][n * LDX + k] = __float2bfloat16(v - __bfloat162float(h));
    }
}

// -------- Stage A: LN + 5 projections (bf16x3), gating, transposed stores ----
__global__ __launch_bounds__(512) void kA(
    const float* __restrict__ x, const float* __restrict__ mask,
    const float* __restrict__ nw_, const float* __restrict__ nb_)
{
    extern __shared__ __align__(16) char smraw[];
    __nv_bfloat16* xh  = (__nv_bfloat16*)smraw;
    __nv_bfloat16* xl  = xh  + 128 * LDX;
    __nv_bfloat16* wPh = xl  + 128 * LDX;
    __nv_bfloat16* wPl = wPh + 128 * LDX;
    __nv_bfloat16* wGh = wPl + 128 * LDX;
    __nv_bfloat16* wGl = wGh + 128 * LDX;
    float* stage = (float*)wGh;                   // aliases wGh/wGl (17408 f)
    float* msk   = (float*)(wGl + 128 * LDX);     // separate 128 floats

    const int tid = threadIdx.x, w = tid >> 5, lane = tid & 31;
    const size_t t0 = (size_t)blockIdx.x * 128;
    const int mw = w & 3, nwp = w >> 2;
    const int m0 = mw * 32, n0 = nwp * 32;

    // LayerNorm 128 tokens, split hi/lo into smem
    float4 nw4 = *(const float4*)&nw_[lane * 4];
    float4 nb4 = *(const float4*)&nb_[lane * 4];
    for (int m = w; m < 128; m += 16) {
        float4 v = *(const float4*)&x[(t0 + m) * 128 + lane * 4];
        float s = v.x + v.y + v.z + v.w;
        float q = v.x*v.x + v.y*v.y + v.z*v.z + v.w*v.w;
        #pragma unroll
        for (int o = 16; o; o >>= 1) {
            s += __shfl_xor_sync(~0u, s, o);
            q += __shfl_xor_sync(~0u, q, o);
        }
        float mu = s * (1.f/128.f);
        float rs = rsqrtf(q * (1.f/128.f) - mu*mu + 1e-5f);
        float y[4] = { (v.x-mu)*rs*nw4.x + nb4.x, (v.y-mu)*rs*nw4.y + nb4.y,
                       (v.z-mu)*rs*nw4.z + nb4.z, (v.w-mu)*rs*nw4.w + nb4.w };
        int base = m * LDX + lane * 4;
        #pragma unroll
        for (int c = 0; c < 4; c++) {
            __nv_bfloat16 h = __float2bfloat16(y[c]);
            xh[base + c] = h;
            xl[base + c] = __float2bfloat16(y[c] - __bfloat162float(h));
        }
    }
    if (tid < 128) msk[tid] = mask[t0 + tid];

    const int PI[3] = { 0, 1, 4 }, GI[3] = { 2, 3, 0 };

    for (int p = 0; p < 3; p++) {
        __syncthreads();
        {   // copy pre-split weights into smem (bf16, vectorized)
            const uint4* sph = (const uint4*)g_wsh[PI[p]];
            const uint4* spl = (const uint4*)g_wsl[PI[p]];
            const uint4* sgh = (const uint4*)g_wsh[GI[p]];
            const uint4* sgl = (const uint4*)g_wsl[GI[p]];
            uint4* dph = (uint4*)wPh; uint4* dpl = (uint4*)wPl;
            uint4* dgh = (uint4*)wGh; uint4* dgl = (uint4*)wGl;
            if (p < 2) {
                for (int i = tid; i < 2176; i += 512) {
                    dph[i] = sph[i]; dpl[i] = spl[i];
                    dgh[i] = sgh[i]; dgl[i] = sgl[i];
                }
            } else {
                for (int i = tid; i < 2176; i += 512) { dph[i] = sph[i]; dpl[i] = spl[i]; }
            }
        }
        __syncthreads();

        wmma::fragment<wmma::accumulator,16,16,16,float> accP[2][2], accG[2][2];
        #pragma unroll
        for (int im = 0; im < 2; im++)
            #pragma unroll
            for (int in = 0; in < 2; in++) {
                wmma::fill_fragment(accP[im][in], 0.f);
                wmma::fill_fragment(accG[im][in], 0.f);
            }
        for (int k0 = 0; k0 < 128; k0 += 16) {
            wmma::fragment<wmma::matrix_a,16,16,16,__nv_bfloat16,wmma::row_major> ah[2], al[2];
            wmma::fragment<wmma::matrix_b,16,16,16,__nv_bfloat16,wmma::col_major> bh[2], bl[2], gh[2], gl[2];
            #pragma unroll
            for (int im = 0; im < 2; im++) {
                wmma::load_matrix_sync(ah[im], xh + (m0+im*16)*LDX + k0, LDX);
                wmma::load_matrix_sync(al[im], xl + (m0+im*16)*LDX + k0, LDX);
            }
            #pragma unroll
            for (int in = 0; in < 2; in++) {
                wmma::load_matrix_sync(bh[in], wPh + (n0+in*16)*LDX + k0, LDX);
                wmma::load_matrix_sync(bl[in], wPl + (n0+in*16)*LDX + k0, LDX);
                if (p < 2) {
                    wmma::load_matrix_sync(gh[in], wGh + (n0+in*16)*LDX + k0, LDX);
                    wmma::load_matrix_sync(gl[in], wGl + (n0+in*16)*LDX + k0, LDX);
                }
            }
            #pragma unroll
            for (int im = 0; im < 2; im++)
                #pragma unroll
                for (int in = 0; in < 2; in++) {
                    wmma::mma_sync(accP[im][in], al[im], bh[in], accP[im][in]);
                    wmma::mma_sync(accP[im][in], ah[im], bl[in], accP[im][in]);
                    wmma::mma_sync(accP[im][in], ah[im], bh[in], accP[im][in]);
                    if (p < 2) {
                        wmma::mma_sync(accG[im][in], al[im], gh[in], accG[im][in]);
                        wmma::mma_sync(accG[im][in], ah[im], gl[in], accG[im][in]);
                        wmma::mma_sync(accG[im][in], ah[im], gh[in], accG[im][in]);
                    }
                }
        }

        if (p < 2) {
            #pragma unroll
            for (int im = 0; im < 2; im++)
                #pragma unroll
                for (int in = 0; in < 2; in++)
                    #pragma unroll
                    for (int t = 0; t < 8; t++)
                        accP[im][in].x[t] *= fsig(accG[im][in].x[t]);
            __syncthreads();   // all warps done reading wG region
            // stage transposed: stageT[n][m], ld 132 (mem_col_major)
            #pragma unroll
            for (int im = 0; im < 2; im++)
                #pragma unroll
                for (int in = 0; in < 2; in++)
                    wmma::store_matrix_sync(stage + (size_t)(n0+in*16)*132 + m0 + im*16,
                                            accP[im][in], 132, wmma::mem_col_major);
            __syncthreads();
            __nv_bfloat16* dst = (p == 0) ? g_leftT : g_rightT;
            for (int e = tid; e < 128 * 128; e += 512) {
                int n = e >> 7, m = e & 127;
                dst[(size_t)n * NTOK + t0 + m] =
                    __float2bfloat16(stage[n * 132 + m] * msk[m]);
            }
        } else {
            #pragma unroll
            for (int im = 0; im < 2; im++)
                #pragma unroll
                for (int in = 0; in < 2; in++) {
                    #pragma unroll
                    for (int t = 0; t < 8; t++)
                        accP[im][in].x[t] = fsig(accP[im][in].x[t]);
                    wmma::store_matrix_sync(
                        g_gate + (t0 + m0 + im*16) * 128 + n0 + in*16,
                        accP[im][in], 128, wmma::mem_row_major);
                }
        }
    }
}

// -------- Stage B: per-channel 768x768x768 bf16 GEMM, cp.async pipelined ----
__global__ __launch_bounds__(256) void kB(void)
{
    extern __shared__ __align__(16) char sbuf[];   // 2 stages x (A,B) x 128x72 bf16
    __nv_bfloat16* sm = (__nv_bfloat16*)sbuf;      // stage s, mat t: sm + (s*2+t)*9216

    const int tid = threadIdx.x, w = tid >> 5, lane = tid & 31;
    const int d = blockIdx.y, ti = blockIdx.x % 6, tj = blockIdx.x / 6;
    const __nv_bfloat16* Lb = g_leftT  + (size_t)d * NTOK + (size_t)ti * 128 * NN;
    const __nv_bfloat16* Rb = g_rightT + (size_t)d * NTOK + (size_t)tj * 128 * NN;
    __nv_bfloat16* Ob = g_outT + (size_t)d * NTOK + (size_t)ti * 128 * NN + tj * 128;

    const int mw = w & 3, nw = w >> 2;
    wmma::fragment<wmma::accumulator,16,16,16,float> acc[2][4];
    #pragma unroll
    for (int im = 0; im < 2; im++)
        #pragma unroll
        for (int in = 0; in < 4; in++) wmma::fill_fragment(acc[im][in], 0.f);

    auto load_stage = [&](int s, int k0) {
        __nv_bfloat16* sA = sm + (s*2 + 0) * 9216;
        __nv_bfloat16* sB = sm + (s*2 + 1) * 9216;
        for (int i = tid; i < 1024; i += 256) {
            int r = i >> 3, c = (i & 7) * 8;
            cp16(&sA[r*72 + c], &Lb[(size_t)r*NN + k0 + c]);
            cp16(&sB[r*72 + c], &Rb[(size_t)r*NN + k0 + c]);
        }
    };

    load_stage(0, 0);
    CP_COMMIT();
    const int NK = NN / 64;  // 12
    for (int i = 0; i < NK; i++) {
        if (i + 1 < NK) { load_stage((i + 1) & 1, (i + 1) * 64); CP_COMMIT(); CP_WAIT(1); }
        else            { CP_WAIT(0); }
        __syncthreads();
        const __nv_bfloat16* sA = sm + ((i & 1)*2 + 0) * 9216;
        const __nv_bfloat16* sB = sm + ((i & 1)*2 + 1) * 9216;
        #pragma unroll
        for (int ks = 0; ks < 64; ks += 16) {
            wmma::fragment<wmma::matrix_a,16,16,16,__nv_bfloat16,wmma::row_major> a[2];
            wmma::fragment<wmma::matrix_b,16,16,16,__nv_bfloat16,wmma::col_major> b[4];
            #pragma unroll
            for (int im = 0; im < 2; im++)
                wmma::load_matrix_sync(a[im], sA + (mw*32 + im*16)*72 + ks, 72);
            #pragma unroll
            for (int in = 0; in < 4; in++)
                wmma::load_matrix_sync(b[in], sB + (nw*64 + in*16)*72 + ks, 72);
            #pragma unroll
            for (int im = 0; im < 2; im++)
                #pragma unroll
                for (int in = 0; in < 4; in++)
                    wmma::mma_sync(acc[im][in], a[im], b[in], acc[im][in]);
        }
        __syncthreads();
    }

    // epilogue: round to bf16 through per-warp smem stage
    float* ws = (float*)sbuf + w * (16 * 68);
    #pragma unroll
    for (int im = 0; im < 2; im++) {
        #pragma unroll
        for (int in = 0; in < 4; in++)
            wmma::store_matrix_sync(ws + in*16, acc[im][in], 68, wmma::mem_row_major);
        __syncwarp();
        int rbase = mw * 32 + im * 16;
        for (int e = lane; e < 16 * 64; e += 32) {
            int r = e >> 6, n = e & 63;
            Ob[(size_t)(rbase + r) * NN + nw*64 + n] = __float2bfloat16(ws[r*68 + n]);
        }
        __syncwarp();
    }
}

// -------- Stage C: channel LN + gate + final projection (bf16x3) ------------
__global__ __launch_bounds__(512) void kC(
    const float* __restrict__ onw, const float* __restrict__ onb,
    float* __restrict__ out)
{
    extern __shared__ __align__(16) char smraw[];
    float* s = (float*)smraw;                          // 128 x 132
    __nv_bfloat16* yh = (__nv_bfloat16*)(s + 128*132);
    __nv_bfloat16* yl = yh + 128 * LDX;
    __nv_bfloat16* wh = yl + 128 * LDX;
    __nv_bfloat16* wl = wh + 128 * LDX;

    const int tid = threadIdx.x, w = tid >> 5, lane = tid & 31;
    const size_t t0 = (size_t)blockIdx.x * 128;

    {   // copy pre-split w_out
        const uint4* sh = (const uint4*)g_wsh[5];
        const uint4* sl = (const uint4*)g_wsl[5];
        uint4* dh = (uint4*)wh; uint4* dl = (uint4*)wl;
        for (int i = tid; i < 2176; i += 512) { dh[i] = sh[i]; dl[i] = sl[i]; }
    }
    for (int idx = tid; idx < 128 * 128; idx += 512) {
        int dch = idx >> 7, m = idx & 127;
        s[m * 132 + dch] = __bfloat162float(g_outT[(size_t)dch * NTOK + t0 + m]);
    }
    __syncthreads();

    float4 w4 = *(const float4*)&onw[lane * 4];
    float4 b4 = *(const float4*)&onb[lane * 4];
    for (int m = w; m < 128; m += 16) {
        float4 v = *(const float4*)&s[m * 132 + lane * 4];
        float ssum = v.x + v.y + v.z + v.w;
        float q = v.x*v.x + v.y*v.y + v.z*v.z + v.w*v.w;
        #pragma unroll
        for (int o = 16; o; o >>= 1) {
            ssum += __shfl_xor_sync(~0u, ssum, o);
            q += __shfl_xor_sync(~0u, q, o);
        }
        float mu = ssum * (1.f/128.f);
        float rs = rsqrtf(q * (1.f/128.f) - mu*mu + 1e-5f);
        float4 g = *(const float4*)&g_gate[(t0 + m) * 128 + lane * 4];
        float* row = &s[m * 132 + lane * 4];
        row[0] = ((v.x-mu)*rs*w4.x + b4.x) * g.x;
        row[1] = ((v.y-mu)*rs*w4.y + b4.y) * g.y;
        row[2] = ((v.z-mu)*rs*w4.z + b4.z) * g.z;
        row[3] = ((v.w-mu)*rs*w4.w + b4.w) * g.w;
    }
    __syncthreads();

    for (int idx = tid; idx < 128 * 128; idx += 512) {
        int m = idx >> 7, h = idx & 127;
        float v = s[m * 132 + h];
        __nv_bfloat16 hv = __float2bfloat16(v);
        yh[m * LDX + h] = hv;
        yl[m * LDX + h] = __float2bfloat16(v - __bfloat162float(hv));
    }
    __syncthreads();

    const int mw = w & 3, nw2 = w >> 2, m0 = mw * 32, n0 = nw2 * 32;
    wmma::fragment<wmma::accumulator,16,16,16,float> acc[2][2];
    #pragma unroll
    for (int im = 0; im < 2; im++)
        #pragma unroll
        for (int in = 0; in < 2; in++) wmma::fill_fragment(acc[im][in], 0.f);

    for (int k0 = 0; k0 < 128; k0 += 16) {
        wmma::fragment<wmma::matrix_a,16,16,16,__nv_bfloat16,wmma::row_major> ah[2], al[2];
        wmma::fragment<wmma::matrix_b,16,16,16,__nv_bfloat16,wmma::col_major> bh[2], bl[2];
        #pragma unroll
        for (int im = 0; im < 2; im++) {
            wmma::load_matrix_sync(ah[im], yh + (m0+im*16)*LDX + k0, LDX);
            wmma::load_matrix_sync(al[im], yl + (m0+im*16)*LDX + k0, LDX);
        }
        #pragma unroll
        for (int in = 0; in < 2; in++) {
            wmma::load_matrix_sync(bh[in], wh + (n0+in*16)*LDX + k0, LDX);
            wmma::load_matrix_sync(bl[in], wl + (n0+in*16)*LDX + k0, LDX);
        }
        #pragma unroll
        for (int im = 0; im < 2; im++)
            #pragma unroll
            for (int in = 0; in < 2; in++) {
                wmma::mma_sync(acc[im][in], al[im], bh[in], acc[im][in]);
                wmma::mma_sync(acc[im][in], ah[im], bl[in], acc[im][in]);
                wmma::mma_sync(acc[im][in], ah[im], bh[in], acc[im][in]);
            }
    }
    #pragma unroll
    for (int im = 0; im < 2; im++)
        #pragma unroll
        for (int in = 0; in < 2; in++)
            wmma::store_matrix_sync(out + (t0 + m0 + im*16) * 128 + n0 + in*16,
                                    acc[im][in], 128, wmma::mem_row_major);
}

extern "C" void kernel_launch(void* const* d_in, const int* in_sizes, int n_in,
                              void* d_out, int out_size) {
    const float* x    = (const float*)d_in[0];
    const float* mask = (const float*)d_in[1];
    const float* nw   = (const float*)d_in[2];
    const float* nb   = (const float*)d_in[3];
    const float* wlft = (const float*)d_in[4];
    const float* wrgt = (const float*)d_in[5];
    const float* wlg  = (const float*)d_in[6];
    const float* wrg  = (const float*)d_in[7];
    const float* wog  = (const float*)d_in[8];
    const float* onw  = (const float*)d_in[9];
    const float* onb  = (const float*)d_in[10];
    const float* wout = (const float*)d_in[11];
    float* out = (float*)d_out;

    size_t smA = 6 * 128 * LDX * sizeof(__nv_bfloat16) + 512;
    size_t smB = 4 * 9216 * sizeof(__nv_bfloat16);   // 73728
    size_t smC = 128 * 132 * sizeof(float) + 4 * 128 * LDX * sizeof(__nv_bfloat16);
    cudaFuncSetAttribute(kA, cudaFuncAttributeMaxDynamicSharedMemorySize, (int)smA);
    cudaFuncSetAttribute(kB, cudaFuncAttributeMaxDynamicSharedMemorySize, (int)smB);
    cudaFuncSetAttribute(kC, cudaFuncAttributeMaxDynamicSharedMemorySize, (int)smC);

    kW<<<6, 256>>>(wlft, wrgt, wlg, wrg, wog, wout);
    kA<<<4608, 512, smA>>>(x, mask, nw, nb);
    kB<<<dim3(36, 128), 256, smB>>>();
    kC<<<4608, 512, smC>>>(onw, onb, out);
}

// round 14
// speedup vs baseline: 2.3050x; 1.0661x over previous
#include <cuda_runtime.h>
#include <cuda_bf16.h>
#include <cuda_fp16.h>
#include <mma.h>
#include <cstdint>

using namespace nvcuda;

static constexpr int NN = 768;
static constexpr size_t NTOK = (size_t)NN * NN;  // 589824

__device__ __align__(256) __nv_bfloat16 g_leftT[128 * 589824];   // [h][tok]
__device__ __align__(256) __nv_bfloat16 g_rightT[128 * 589824];  // [h][tok]
__device__ __align__(256) __half        g_gate[589824 * 128];    // [tok][h] fp16
__device__ __align__(256) __nv_bfloat16 g_outT[128 * 589824];    // [d][i*768+j]

#define LDX 136
// pre-split weights: 0=wl 1=wr 2=wlg 3=wrg 4=wog 5=wout
__device__ __align__(256) __nv_bfloat16 g_wsh[6][128 * LDX];
__device__ __align__(256) __nv_bfloat16 g_wsl[6][128 * LDX];

__device__ __forceinline__ float fsig(float z) { return 1.f / (1.f + __expf(-z)); }

__device__ __forceinline__ void cp16(void* smem, const void* g) {
    unsigned int s = (unsigned int)__cvta_generic_to_shared(smem);
    asm volatile("cp.async.cg.shared.global [%0], [%1], 16;\n" :: "r"(s), "l"(g));
}
#define CP_COMMIT() asm volatile("cp.async.commit_group;\n")
#define CP_WAIT(n)  asm volatile("cp.async.wait_group %0;\n" :: "n"(n))

// -------- Stage W: split 6 weight matrices into bf16 hi/lo ------------------
__global__ __launch_bounds__(256) void kW(
    const float* __restrict__ wl, const float* __restrict__ wr,
    const float* __restrict__ wlg, const float* __restrict__ wrg,
    const float* __restrict__ wog, const float* __restrict__ wout)
{
    const float* Ws[6] = { wl, wr, wlg, wrg, wog, wout };
    const float* W = Ws[blockIdx.x];
    for (int idx = threadIdx.x; idx < 128 * 128; idx += 256) {
        int n = idx >> 7, k = idx & 127;
        float v = W[idx];
        __nv_bfloat16 h = __float2bfloat16(v);
        g_wsh[blockIdx.x][n * LDX + k] = h;
        g_wsl[blockIdx.x][n * LDX + k] = __float2bfloat16(v - __bfloat162float(h));
    }
}

// -------- Stage A: LN + 5 projections (bf16x3), gating, transposed stores ----
__global__ __launch_bounds__(512) void kA(
    const float* __restrict__ x, const float* __restrict__ mask,
    const float* __restrict__ nw_, const float* __restrict__ nb_)
{
    extern __shared__ __align__(16) char smraw[];
    __nv_bfloat16* xh  = (__nv_bfloat16*)smraw;
    __nv_bfloat16* xl  = xh  + 128 * LDX;
    __nv_bfloat16* wPh = xl  + 128 * LDX;
    __nv_bfloat16* wPl = wPh + 128 * LDX;
    __nv_bfloat16* wGh = wPl + 128 * LDX;
    __nv_bfloat16* wGl = wGh + 128 * LDX;
    float* stage = (float*)wGh;                   // aliases wGh/wGl (17408 f)
    float* msk   = (float*)(wGl + 128 * LDX);     // separate 128 floats

    const int tid = threadIdx.x, w = tid >> 5, lane = tid & 31;
    const size_t t0 = (size_t)blockIdx.x * 128;
    const int mw = w & 3, nwp = w >> 2;
    const int m0 = mw * 32, n0 = nwp * 32;

    // LayerNorm 128 tokens, split hi/lo into smem
    float4 nw4 = *(const float4*)&nw_[lane * 4];
    float4 nb4 = *(const float4*)&nb_[lane * 4];
    for (int m = w; m < 128; m += 16) {
        float4 v = *(const float4*)&x[(t0 + m) * 128 + lane * 4];
        float s = v.x + v.y + v.z + v.w;
        float q = v.x*v.x + v.y*v.y + v.z*v.z + v.w*v.w;
        #pragma unroll
        for (int o = 16; o; o >>= 1) {
            s += __shfl_xor_sync(~0u, s, o);
            q += __shfl_xor_sync(~0u, q, o);
        }
        float mu = s * (1.f/128.f);
        float rs = rsqrtf(q * (1.f/128.f) - mu*mu + 1e-5f);
        float y[4] = { (v.x-mu)*rs*nw4.x + nb4.x, (v.y-mu)*rs*nw4.y + nb4.y,
                       (v.z-mu)*rs*nw4.z + nb4.z, (v.w-mu)*rs*nw4.w + nb4.w };
        int base = m * LDX + lane * 4;
        #pragma unroll
        for (int c = 0; c < 4; c++) {
            __nv_bfloat16 h = __float2bfloat16(y[c]);
            xh[base + c] = h;
            xl[base + c] = __float2bfloat16(y[c] - __bfloat162float(h));
        }
    }
    if (tid < 128) msk[tid] = mask[t0 + tid];

    const int PI[3] = { 0, 1, 4 }, GI[3] = { 2, 3, 0 };

    for (int p = 0; p < 3; p++) {
        __syncthreads();
        {   // copy pre-split weights into smem (bf16, vectorized)
            const uint4* sph = (const uint4*)g_wsh[PI[p]];
            const uint4* spl = (const uint4*)g_wsl[PI[p]];
            const uint4* sgh = (const uint4*)g_wsh[GI[p]];
            const uint4* sgl = (const uint4*)g_wsl[GI[p]];
            uint4* dph = (uint4*)wPh; uint4* dpl = (uint4*)wPl;
            uint4* dgh = (uint4*)wGh; uint4* dgl = (uint4*)wGl;
            if (p < 2) {
                for (int i = tid; i < 2176; i += 512) {
                    dph[i] = sph[i]; dpl[i] = spl[i];
                    dgh[i] = sgh[i]; dgl[i] = sgl[i];
                }
            } else {
                for (int i = tid; i < 2176; i += 512) { dph[i] = sph[i]; dpl[i] = spl[i]; }
            }
        }
        __syncthreads();

        wmma::fragment<wmma::accumulator,16,16,16,float> accP[2][2], accG[2][2];
        #pragma unroll
        for (int im = 0; im < 2; im++)
            #pragma unroll
            for (int in = 0; in < 2; in++) {
                wmma::fill_fragment(accP[im][in], 0.f);
                wmma::fill_fragment(accG[im][in], 0.f);
            }
        for (int k0 = 0; k0 < 128; k0 += 16) {
            wmma::fragment<wmma::matrix_a,16,16,16,__nv_bfloat16,wmma::row_major> ah[2], al[2];
            wmma::fragment<wmma::matrix_b,16,16,16,__nv_bfloat16,wmma::col_major> bh[2], bl[2], gh[2], gl[2];
            #pragma unroll
            for (int im = 0; im < 2; im++) {
                wmma::load_matrix_sync(ah[im], xh + (m0+im*16)*LDX + k0, LDX);
                wmma::load_matrix_sync(al[im], xl + (m0+im*16)*LDX + k0, LDX);
            }
            #pragma unroll
            for (int in = 0; in < 2; in++) {
                wmma::load_matrix_sync(bh[in], wPh + (n0+in*16)*LDX + k0, LDX);
                wmma::load_matrix_sync(bl[in], wPl + (n0+in*16)*LDX + k0, LDX);
                if (p < 2) {
                    wmma::load_matrix_sync(gh[in], wGh + (n0+in*16)*LDX + k0, LDX);
                    wmma::load_matrix_sync(gl[in], wGl + (n0+in*16)*LDX + k0, LDX);
                }
            }
            #pragma unroll
            for (int im = 0; im < 2; im++)
                #pragma unroll
                for (int in = 0; in < 2; in++) {
                    wmma::mma_sync(accP[im][in], al[im], bh[in], accP[im][in]);
                    wmma::mma_sync(accP[im][in], ah[im], bl[in], accP[im][in]);
                    wmma::mma_sync(accP[im][in], ah[im], bh[in], accP[im][in]);
                    if (p < 2) {
                        wmma::mma_sync(accG[im][in], al[im], gh[in], accG[im][in]);
                        wmma::mma_sync(accG[im][in], ah[im], gl[in], accG[im][in]);
                        wmma::mma_sync(accG[im][in], ah[im], gh[in], accG[im][in]);
                    }
                }
        }

        if (p < 2) {
            #pragma unroll
            for (int im = 0; im < 2; im++)
                #pragma unroll
                for (int in = 0; in < 2; in++)
                    #pragma unroll
                    for (int t = 0; t < 8; t++)
                        accP[im][in].x[t] *= fsig(accG[im][in].x[t]);
            __syncthreads();   // all warps done reading wG region
            // stage transposed: stageT[n][m], ld 132 (mem_col_major)
            #pragma unroll
            for (int im = 0; im < 2; im++)
                #pragma unroll
                for (int in = 0; in < 2; in++)
                    wmma::store_matrix_sync(stage + (size_t)(n0+in*16)*132 + m0 + im*16,
                                            accP[im][in], 132, wmma::mem_col_major);
            __syncthreads();
            __nv_bfloat16* dst = (p == 0) ? g_leftT : g_rightT;
            for (int e = tid; e < 128 * 128; e += 512) {
                int n = e >> 7, m = e & 127;
                dst[(size_t)n * NTOK + t0 + m] =
                    __float2bfloat16(stage[n * 132 + m] * msk[m]);
            }
        } else {
            // out_gate: sigmoid -> fp16, staged for coalesced half2 stores
            #pragma unroll
            for (int im = 0; im < 2; im++)
                #pragma unroll
                for (int in = 0; in < 2; in++) {
                    #pragma unroll
                    for (int t = 0; t < 8; t++)
                        accP[im][in].x[t] = fsig(accP[im][in].x[t]);
                    wmma::store_matrix_sync(stage + (m0+im*16)*136 + n0 + in*16,
                                            accP[im][in], 136, wmma::mem_row_major);
                }
            __syncthreads();
            for (int e = tid; e < 128 * 64; e += 512) {
                int m = e >> 6, hp = e & 63;
                __half2 hv = __halves2half2(__float2half(stage[m*136 + hp*2]),
                                            __float2half(stage[m*136 + hp*2 + 1]));
                *(__half2*)&g_gate[(t0 + m) * 128 + hp*2] = hv;
            }
        }
    }
}

// -------- Stage B: per-channel 768x768x768 bf16 GEMM, 3-stage cp.async ------
// Race-free single-sync pipeline: WAIT -> sync -> issue next load -> compute.
// The load issued at iter i targets slot (i+2)%3 == (i-1)%3; the sync proves
// every warp finished iter i-1's compute of that slot before it's overwritten.
__global__ __launch_bounds__(256) void kB(void)
{
    extern __shared__ __align__(16) char sbuf[];   // 3 stages x (A,B) x 128x72 bf16
    __nv_bfloat16* sm = (__nv_bfloat16*)sbuf;      // stage s, mat t: sm + (s*2+t)*9216

    const int tid = threadIdx.x, w = tid >> 5, lane = tid & 31;
    const int d = blockIdx.y, ti = blockIdx.x % 6, tj = blockIdx.x / 6;
    const __nv_bfloat16* Lb = g_leftT  + (size_t)d * NTOK + (size_t)ti * 128 * NN;
    const __nv_bfloat16* Rb = g_rightT + (size_t)d * NTOK + (size_t)tj * 128 * NN;
    __nv_bfloat16* Ob = g_outT + (size_t)d * NTOK + (size_t)ti * 128 * NN + tj * 128;

    const int mw = w & 3, nw = w >> 2;
    wmma::fragment<wmma::accumulator,16,16,16,float> acc[2][4];
    #pragma unroll
    for (int im = 0; im < 2; im++)
        #pragma unroll
        for (int in = 0; in < 4; in++) wmma::fill_fragment(acc[im][in], 0.f);

    auto load_stage = [&](int s, int k0) {
        __nv_bfloat16* sA = sm + (s*2 + 0) * 9216;
        __nv_bfloat16* sB = sm + (s*2 + 1) * 9216;
        for (int i = tid; i < 1024; i += 256) {
            int r = i >> 3, c = (i & 7) * 8;
            cp16(&sA[r*72 + c], &Lb[(size_t)r*NN + k0 + c]);
            cp16(&sB[r*72 + c], &Rb[(size_t)r*NN + k0 + c]);
        }
    };

    load_stage(0, 0);   CP_COMMIT();
    load_stage(1, 64);  CP_COMMIT();
    const int NK = NN / 64;  // 12
    for (int i = 0; i < NK; i++) {
        if (i + 1 < NK) { CP_WAIT(1); } else { CP_WAIT(0); }
        __syncthreads();   // stage i visible to all; all warps done with iter i-1
        if (i + 2 < NK) { load_stage((i + 2) % 3, (i + 2) * 64); CP_COMMIT(); }
        const __nv_bfloat16* sA = sm + ((i % 3)*2 + 0) * 9216;
        const __nv_bfloat16* sB = sm + ((i % 3)*2 + 1) * 9216;
        #pragma unroll
        for (int ks = 0; ks < 64; ks += 16) {
            wmma::fragment<wmma::matrix_a,16,16,16,__nv_bfloat16,wmma::row_major> a[2];
            wmma::fragment<wmma::matrix_b,16,16,16,__nv_bfloat16,wmma::col_major> b[4];
            #pragma unroll
            for (int im = 0; im < 2; im++)
                wmma::load_matrix_sync(a[im], sA + (mw*32 + im*16)*72 + ks, 72);
            #pragma unroll
            for (int in = 0; in < 4; in++)
                wmma::load_matrix_sync(b[in], sB + (nw*64 + in*16)*72 + ks, 72);
            #pragma unroll
            for (int im = 0; im < 2; im++)
                #pragma unroll
                for (int in = 0; in < 4; in++)
                    wmma::mma_sync(acc[im][in], a[im], b[in], acc[im][in]);
        }
    }

    // epilogue: last compute read stage (NK-1)%3 = 2 (bytes 73728+); the
    // per-warp stage buffers below use bytes 0..34816 -> no overlap with any
    // warp still in the final MMA. Sync anyway for the write/read handoff.
    __syncthreads();
    float* ws = (float*)sbuf + w * (16 * 68);
    #pragma unroll
    for (int im = 0; im < 2; im++) {
        #pragma unroll
        for (int in = 0; in < 4; in++)
            wmma::store_matrix_sync(ws + in*16, acc[im][in], 68, wmma::mem_row_major);
        __syncwarp();
        int rbase = mw * 32 + im * 16;
        for (int e = lane; e < 16 * 64; e += 32) {
            int r = e >> 6, n = e & 63;
            Ob[(size_t)(rbase + r) * NN + nw*64 + n] = __float2bfloat16(ws[r*68 + n]);
        }
        __syncwarp();
    }
}

// -------- Stage C: channel LN + gate + final projection (bf16x3) ------------
// 64-token blocks, 256 threads, y-buffers alias the fp32 staging buffer.
__global__ __launch_bounds__(256) void kC(
    const float* __restrict__ onw, const float* __restrict__ onb,
    float* __restrict__ out)
{
    extern __shared__ __align__(16) char smraw[];
    float* s = (float*)smraw;                          // 64 x 140 fp32 (35840 B)
    __nv_bfloat16* yh = (__nv_bfloat16*)smraw;         // 64 x 136 (alias over s)
    __nv_bfloat16* yl = yh + 64 * LDX;
    __nv_bfloat16* wh = (__nv_bfloat16*)(smraw + 35840);
    __nv_bfloat16* wl = wh + 128 * LDX;

    const int tid = threadIdx.x, w = tid >> 5, lane = tid & 31;
    const size_t t0 = (size_t)blockIdx.x * 64;

    {   // copy pre-split w_out
        const uint4* sh = (const uint4*)g_wsh[5];
        const uint4* sl = (const uint4*)g_wsl[5];
        uint4* dh = (uint4*)wh; uint4* dl = (uint4*)wl;
        for (int i = tid; i < 2176; i += 256) { dh[i] = sh[i]; dl[i] = sl[i]; }
    }
    // gather transposed einsum output: s[m][d]
    for (int idx = tid; idx < 64 * 128; idx += 256) {
        int m = idx & 63, dch = idx >> 6;
        s[m * 140 + dch] = __bfloat162float(g_outT[(size_t)dch * NTOK + t0 + m]);
    }
    __syncthreads();

    // LN over channels + gate, results parked in registers
    float4 w4 = *(const float4*)&onw[lane * 4];
    float4 b4 = *(const float4*)&onb[lane * 4];
    float rv[8][4];
    #pragma unroll
    for (int k = 0; k < 8; k++) {
        int m = w + k * 8;
        float4 v = *(const float4*)&s[m * 140 + lane * 4];
        float ssum = v.x + v.y + v.z + v.w;
        float q = v.x*v.x + v.y*v.y + v.z*v.z + v.w*v.w;
        #pragma unroll
        for (int o = 16; o; o >>= 1) {
            ssum += __shfl_xor_sync(~0u, ssum, o);
            q += __shfl_xor_sync(~0u, q, o);
        }
        float mu = ssum * (1.f/128.f);
        float rs = rsqrtf(q * (1.f/128.f) - mu*mu + 1e-5f);
        const __half2* gp = (const __half2*)&g_gate[(t0 + m) * 128];
        float2 g0 = __half22float2(gp[lane*2]);
        float2 g1 = __half22float2(gp[lane*2 + 1]);
        rv[k][0] = ((v.x-mu)*rs*w4.x + b4.x) * g0.x;
        rv[k][1] = ((v.y-mu)*rs*w4.y + b4.y) * g0.y;
        rv[k][2] = ((v.z-mu)*rs*w4.z + b4.z) * g1.x;
        rv[k][3] = ((v.w-mu)*rs*w4.w + b4.w) * g1.y;
    }
    __syncthreads();   // everyone done reading s -> safe to alias

    #pragma unroll
    for (int k = 0; k < 8; k++) {
        int m = w + k * 8;
        int base = m * LDX + lane * 4;
        #pragma unroll
        for (int c = 0; c < 4; c++) {
            __nv_bfloat16 h = __float2bfloat16(rv[k][c]);
            yh[base + c] = h;
            yl[base + c] = __float2bfloat16(rv[k][c] - __bfloat162float(h));
        }
    }
    __syncthreads();

    // projection: 64 x 128 x 128 (bf16x3)
    const int mw = w & 1, nw2 = w >> 1, m0 = mw * 32, n0 = nw2 * 32;
    wmma::fragment<wmma::accumulator,16,16,16,float> acc[2][2];
    #pragma unroll
    for (int im = 0; im < 2; im++)
        #pragma unroll
        for (int in = 0; in < 2; in++) wmma::fill_fragment(acc[im][in], 0.f);

    for (int k0 = 0; k0 < 128; k0 += 16) {
        wmma::fragment<wmma::matrix_a,16,16,16,__nv_bfloat16,wmma::row_major> ah[2], al[2];
        wmma::fragment<wmma::matrix_b,16,16,16,__nv_bfloat16,wmma::col_major> bh[2], bl[2];
        #pragma unroll
        for (int im = 0; im < 2; im++) {
            wmma::load_matrix_sync(ah[im], yh + (m0+im*16)*LDX + k0, LDX);
            wmma::load_matrix_sync(al[im], yl + (m0+im*16)*LDX + k0, LDX);
        }
        #pragma unroll
        for (int in = 0; in < 2; in++) {
            wmma::load_matrix_sync(bh[in], wh + (n0+in*16)*LDX + k0, LDX);
            wmma::load_matrix_sync(bl[in], wl + (n0+in*16)*LDX + k0, LDX);
        }
        #pragma unroll
        for (int im = 0; im < 2; im++)
            #pragma unroll
            for (int in = 0; in < 2; in++) {
                wmma::mma_sync(acc[im][in], al[im], bh[in], acc[im][in]);
                wmma::mma_sync(acc[im][in], ah[im], bl[in], acc[im][in]);
                wmma::mma_sync(acc[im][in], ah[im], bh[in], acc[im][in]);
            }
    }
    #pragma unroll
    for (int im = 0; im < 2; im++)
        #pragma unroll
        for (int in = 0; in < 2; in++)
            wmma::store_matrix_sync(out + (t0 + m0 + im*16) * 128 + n0 + in*16,
                                    acc[im][in], 128, wmma::mem_row_major);
}

extern "C" void kernel_launch(void* const* d_in, const int* in_sizes, int n_in,
                              void* d_out, int out_size) {
    const float* x    = (const float*)d_in[0];
    const float* mask = (const float*)d_in[1];
    const float* nw   = (const float*)d_in[2];
    const float* nb   = (const float*)d_in[3];
    const float* wlft = (const float*)d_in[4];
    const float* wrgt = (const float*)d_in[5];
    const float* wlg  = (const float*)d_in[6];
    const float* wrg  = (const float*)d_in[7];
    const float* wog  = (const float*)d_in[8];
    const float* onw  = (const float*)d_in[9];
    const float* onb  = (const float*)d_in[10];
    const float* wout = (const float*)d_in[11];
    float* out = (float*)d_out;

    size_t smA = 6 * 128 * LDX * sizeof(__nv_bfloat16) + 512;
    size_t smB = 6 * 9216 * sizeof(__nv_bfloat16);                 // 110592
    size_t smC = 35840 + 2 * 128 * LDX * sizeof(__nv_bfloat16);    // 105472
    cudaFuncSetAttribute(kA, cudaFuncAttributeMaxDynamicSharedMemorySize, (int)smA);
    cudaFuncSetAttribute(kB, cudaFuncAttributeMaxDynamicSharedMemorySize, (int)smB);
    cudaFuncSetAttribute(kC, cudaFuncAttributeMaxDynamicSharedMemorySize, (int)smC);

    kW<<<6, 256>>>(wlft, wrgt, wlg, wrg, wog, wout);
    kA<<<4608, 512, smA>>>(x, mask, nw, nb);
    kB<<<dim3(36, 128), 256, smB>>>();
    kC<<<9216, 256, smC>>>(onw, onb, out);
}

// round 16
// speedup vs baseline: 2.3953x; 1.0392x over previous
#include <cuda_runtime.h>
#include <cuda_bf16.h>
#include <cuda_fp16.h>
#include <mma.h>
#include <cstdint>

using namespace nvcuda;

static constexpr int NN = 768;
static constexpr size_t NTOK = (size_t)NN * NN;  // 589824

__device__ __align__(256) __nv_bfloat16 g_leftT[128 * 589824];   // [h][tok]
__device__ __align__(256) __nv_bfloat16 g_rightT[128 * 589824];  // [h][tok]
__device__ __align__(256) __half        g_gate[589824 * 128];    // [tok][h] fp16
__device__ __align__(256) __nv_bfloat16 g_outT[128 * 589824];    // [d][i*768+j]

#define LDX 136
// pre-split weights: 0=wl 1=wr 2=wlg 3=wrg 4=wog 5=wout
__device__ __align__(256) __nv_bfloat16 g_wsh[6][128 * LDX];
__device__ __align__(256) __nv_bfloat16 g_wsl[6][128 * LDX];

__device__ __forceinline__ float fsig(float z) { return 1.f / (1.f + __expf(-z)); }

__device__ __forceinline__ void cp16(void* smem, const void* g) {
    unsigned int s = (unsigned int)__cvta_generic_to_shared(smem);
    asm volatile("cp.async.cg.shared.global [%0], [%1], 16;\n" :: "r"(s), "l"(g));
}
#define CP_COMMIT() asm volatile("cp.async.commit_group;\n")
#define CP_WAIT(n)  asm volatile("cp.async.wait_group %0;\n" :: "n"(n))

// -------- Stage W: split 6 weight matrices into bf16 hi/lo ------------------
__global__ __launch_bounds__(256) void kW(
    const float* __restrict__ wl, const float* __restrict__ wr,
    const float* __restrict__ wlg, const float* __restrict__ wrg,
    const float* __restrict__ wog, const float* __restrict__ wout)
{
    const float* Ws[6] = { wl, wr, wlg, wrg, wog, wout };
    const float* W = Ws[blockIdx.x];
    for (int idx = threadIdx.x; idx < 128 * 128; idx += 256) {
        int n = idx >> 7, k = idx & 127;
        float v = W[idx];
        __nv_bfloat16 h = __float2bfloat16(v);
        g_wsh[blockIdx.x][n * LDX + k] = h;
        g_wsl[blockIdx.x][n * LDX + k] = __float2bfloat16(v - __bfloat162float(h));
    }
}

// -------- Stage A: LN + 5 projections (bf16x3), weights direct from global --
__global__ __launch_bounds__(512) void kA(
    const float* __restrict__ x, const float* __restrict__ mask,
    const float* __restrict__ nw_, const float* __restrict__ nb_)
{
    extern __shared__ __align__(16) char smraw[];
    __nv_bfloat16* xh  = (__nv_bfloat16*)smraw;
    __nv_bfloat16* xl  = xh  + 128 * LDX;
    float* stage = (float*)(xl + 128 * LDX);      // 17408 floats (69632 B)
    float* msk   = stage + 17408;                 // 128 floats

    const int tid = threadIdx.x, w = tid >> 5, lane = tid & 31;
    const size_t t0 = (size_t)blockIdx.x * 128;
    const int mw = w & 3, nwp = w >> 2;
    const int m0 = mw * 32, n0 = nwp * 32;

    // LayerNorm 128 tokens, split hi/lo into smem
    float4 nw4 = *(const float4*)&nw_[lane * 4];
    float4 nb4 = *(const float4*)&nb_[lane * 4];
    for (int m = w; m < 128; m += 16) {
        float4 v = *(const float4*)&x[(t0 + m) * 128 + lane * 4];
        float s = v.x + v.y + v.z + v.w;
        float q = v.x*v.x + v.y*v.y + v.z*v.z + v.w*v.w;
        #pragma unroll
        for (int o = 16; o; o >>= 1) {
            s += __shfl_xor_sync(~0u, s, o);
            q += __shfl_xor_sync(~0u, q, o);
        }
        float mu = s * (1.f/128.f);
        float rs = rsqrtf(q * (1.f/128.f) - mu*mu + 1e-5f);
        float y[4] = { (v.x-mu)*rs*nw4.x + nb4.x, (v.y-mu)*rs*nw4.y + nb4.y,
                       (v.z-mu)*rs*nw4.z + nb4.z, (v.w-mu)*rs*nw4.w + nb4.w };
        int base = m * LDX + lane * 4;
        #pragma unroll
        for (int c = 0; c < 4; c++) {
            __nv_bfloat16 h = __float2bfloat16(y[c]);
            xh[base + c] = h;
            xl[base + c] = __float2bfloat16(y[c] - __bfloat162float(h));
        }
    }
    if (tid < 128) msk[tid] = mask[t0 + tid];
    __syncthreads();

    const int PI[3] = { 0, 1, 4 }, GI[3] = { 2, 3, 0 };

    for (int p = 0; p < 3; p++) {
        const __nv_bfloat16* WPh = g_wsh[PI[p]];
        const __nv_bfloat16* WPl = g_wsl[PI[p]];
        const __nv_bfloat16* WGh = g_wsh[GI[p]];
        const __nv_bfloat16* WGl = g_wsl[GI[p]];

        wmma::fragment<wmma::accumulator,16,16,16,float> accP[2][2], accG[2][2];
        #pragma unroll
        for (int im = 0; im < 2; im++)
            #pragma unroll
            for (int in = 0; in < 2; in++) {
                wmma::fill_fragment(accP[im][in], 0.f);
                wmma::fill_fragment(accG[im][in], 0.f);
            }
        for (int k0 = 0; k0 < 128; k0 += 16) {
            wmma::fragment<wmma::matrix_a,16,16,16,__nv_bfloat16,wmma::row_major> ah[2], al[2];
            wmma::fragment<wmma::matrix_b,16,16,16,__nv_bfloat16,wmma::col_major> bh[2], bl[2], gh[2], gl[2];
            #pragma unroll
            for (int im = 0; im < 2; im++) {
                wmma::load_matrix_sync(ah[im], xh + (m0+im*16)*LDX + k0, LDX);
                wmma::load_matrix_sync(al[im], xl + (m0+im*16)*LDX + k0, LDX);
            }
            #pragma unroll
            for (int in = 0; in < 2; in++) {
                wmma::load_matrix_sync(bh[in], WPh + (n0+in*16)*LDX + k0, LDX);
                wmma::load_matrix_sync(bl[in], WPl + (n0+in*16)*LDX + k0, LDX);
                if (p < 2) {
                    wmma::load_matrix_sync(gh[in], WGh + (n0+in*16)*LDX + k0, LDX);
                    wmma::load_matrix_sync(gl[in], WGl + (n0+in*16)*LDX + k0, LDX);
                }
            }
            #pragma unroll
            for (int im = 0; im < 2; im++)
                #pragma unroll
                for (int in = 0; in < 2; in++) {
                    wmma::mma_sync(accP[im][in], al[im], bh[in], accP[im][in]);
                    wmma::mma_sync(accP[im][in], ah[im], bl[in], accP[im][in]);
                    wmma::mma_sync(accP[im][in], ah[im], bh[in], accP[im][in]);
                    if (p < 2) {
                        wmma::mma_sync(accG[im][in], al[im], gh[in], accG[im][in]);
                        wmma::mma_sync(accG[im][in], ah[im], gl[in], accG[im][in]);
                        wmma::mma_sync(accG[im][in], ah[im], gh[in], accG[im][in]);
                    }
                }
        }

        if (p < 2) {
            #pragma unroll
            for (int im = 0; im < 2; im++)
                #pragma unroll
                for (int in = 0; in < 2; in++)
                    #pragma unroll
                    for (int t = 0; t < 8; t++)
                        accP[im][in].x[t] *= fsig(accG[im][in].x[t]);
            __syncthreads();   // stage free (prior pass writers done)
            // stage transposed: stageT[n][m], ld 132 (mem_col_major)
            #pragma unroll
            for (int im = 0; im < 2; im++)
                #pragma unroll
                for (int in = 0; in < 2; in++)
                    wmma::store_matrix_sync(stage + (size_t)(n0+in*16)*132 + m0 + im*16,
                                            accP[im][in], 132, wmma::mem_col_major);
            __syncthreads();
            __nv_bfloat16* dst = (p == 0) ? g_leftT : g_rightT;
            for (int e = tid; e < 128 * 128; e += 512) {
                int n = e >> 7, m = e & 127;
                dst[(size_t)n * NTOK + t0 + m] =
                    __float2bfloat16(stage[n * 132 + m] * msk[m]);
            }
        } else {
            // out_gate: sigmoid -> fp16, staged for coalesced half2 stores
            #pragma unroll
            for (int im = 0; im < 2; im++)
                #pragma unroll
                for (int in = 0; in < 2; in++)
                    #pragma unroll
                    for (int t = 0; t < 8; t++)
                        accP[im][in].x[t] = fsig(accP[im][in].x[t]);
            __syncthreads();
            #pragma unroll
            for (int im = 0; im < 2; im++)
                #pragma unroll
                for (int in = 0; in < 2; in++)
                    wmma::store_matrix_sync(stage + (m0+im*16)*136 + n0 + in*16,
                                            accP[im][in], 136, wmma::mem_row_major);
            __syncthreads();
            for (int e = tid; e < 128 * 64; e += 512) {
                int m = e >> 6, hp = e & 63;
                __half2 hv = __halves2half2(__float2half(stage[m*136 + hp*2]),
                                            __float2half(stage[m*136 + hp*2 + 1]));
                *(__half2*)&g_gate[(t0 + m) * 128 + hp*2] = hv;
            }
        }
    }
}

// -------- Stage B: per-channel 768x768x768 bf16 GEMM, 3-stage cp.async ------
// Race-free single-sync pipeline: WAIT -> sync -> issue next load -> compute.
__global__ __launch_bounds__(256) void kB(void)
{
    extern __shared__ __align__(16) char sbuf[];   // 3 stages x (A,B) x 128x72 bf16
    __nv_bfloat16* sm = (__nv_bfloat16*)sbuf;      // stage s, mat t: sm + (s*2+t)*9216

    const int tid = threadIdx.x, w = tid >> 5, lane = tid & 31;
    const int d = blockIdx.y, ti = blockIdx.x % 6, tj = blockIdx.x / 6;
    const __nv_bfloat16* Lb = g_leftT  + (size_t)d * NTOK + (size_t)ti * 128 * NN;
    const __nv_bfloat16* Rb = g_rightT + (size_t)d * NTOK + (size_t)tj * 128 * NN;
    __nv_bfloat16* Ob = g_outT + (size_t)d * NTOK + (size_t)ti * 128 * NN + tj * 128;

    const int mw = w & 3, nw = w >> 2;
    wmma::fragment<wmma::accumulator,16,16,16,float> acc[2][4];
    #pragma unroll
    for (int im = 0; im < 2; im++)
        #pragma unroll
        for (int in = 0; in < 4; in++) wmma::fill_fragment(acc[im][in], 0.f);

    auto load_stage = [&](int s, int k0) {
        __nv_bfloat16* sA = sm + (s*2 + 0) * 9216;
        __nv_bfloat16* sB = sm + (s*2 + 1) * 9216;
        for (int i = tid; i < 1024; i += 256) {
            int r = i >> 3, c = (i & 7) * 8;
            cp16(&sA[r*72 + c], &Lb[(size_t)r*NN + k0 + c]);
            cp16(&sB[r*72 + c], &Rb[(size_t)r*NN + k0 + c]);
        }
    };

    load_stage(0, 0);   CP_COMMIT();
    load_stage(1, 64);  CP_COMMIT();
    const int NK = NN / 64;  // 12
    for (int i = 0; i < NK; i++) {
        if (i + 1 < NK) { CP_WAIT(1); } else { CP_WAIT(0); }
        __syncthreads();   // stage i visible; all warps done with iter i-1
        if (i + 2 < NK) { load_stage((i + 2) % 3, (i + 2) * 64); CP_COMMIT(); }
        const __nv_bfloat16* sA = sm + ((i % 3)*2 + 0) * 9216;
        const __nv_bfloat16* sB = sm + ((i % 3)*2 + 1) * 9216;
        #pragma unroll
        for (int ks = 0; ks < 64; ks += 16) {
            wmma::fragment<wmma::matrix_a,16,16,16,__nv_bfloat16,wmma::row_major> a[2];
            wmma::fragment<wmma::matrix_b,16,16,16,__nv_bfloat16,wmma::col_major> b[4];
            #pragma unroll
            for (int im = 0; im < 2; im++)
                wmma::load_matrix_sync(a[im], sA + (mw*32 + im*16)*72 + ks, 72);
            #pragma unroll
            for (int in = 0; in < 4; in++)
                wmma::load_matrix_sync(b[in], sB + (nw*64 + in*16)*72 + ks, 72);
            #pragma unroll
            for (int im = 0; im < 2; im++)
                #pragma unroll
                for (int in = 0; in < 4; in++)
                    wmma::mma_sync(acc[im][in], a[im], b[in], acc[im][in]);
        }
    }

    __syncthreads();
    float* ws = (float*)sbuf + w * (16 * 68);
    #pragma unroll
    for (int im = 0; im < 2; im++) {
        #pragma unroll
        for (int in = 0; in < 4; in++)
            wmma::store_matrix_sync(ws + in*16, acc[im][in], 68, wmma::mem_row_major);
        __syncwarp();
        int rbase = mw * 32 + im * 16;
        for (int e = lane; e < 16 * 64; e += 32) {
            int r = e >> 6, n = e & 63;
            Ob[(size_t)(rbase + r) * NN + nw*64 + n] = __float2bfloat16(ws[r*68 + n]);
        }
        __syncwarp();
    }
}

// -------- Stage C: channel LN + gate + final projection (bf16x3) ------------
// 64-token blocks, 256 threads; w_out fragments loaded straight from global.
__global__ __launch_bounds__(256) void kC(
    const float* __restrict__ onw, const float* __restrict__ onb,
    float* __restrict__ out)
{
    extern __shared__ __align__(16) char smraw[];
    float* s = (float*)smraw;                          // 64 x 140 fp32 (35840 B)
    __nv_bfloat16* yh = (__nv_bfloat16*)smraw;         // 64 x 136 (alias over s)
    __nv_bfloat16* yl = yh + 64 * LDX;

    const int tid = threadIdx.x, w = tid >> 5, lane = tid & 31;
    const size_t t0 = (size_t)blockIdx.x * 64;

    // gather transposed einsum output: s[m][d]
    for (int idx = tid; idx < 64 * 128; idx += 256) {
        int m = idx & 63, dch = idx >> 6;
        s[m * 140 + dch] = __bfloat162float(g_outT[(size_t)dch * NTOK + t0 + m]);
    }
    __syncthreads();

    // LN over channels + gate, results parked in registers
    float4 w4 = *(const float4*)&onw[lane * 4];
    float4 b4 = *(const float4*)&onb[lane * 4];
    float rv[8][4];
    #pragma unroll
    for (int k = 0; k < 8; k++) {
        int m = w + k * 8;
        float4 v = *(const float4*)&s[m * 140 + lane * 4];
        float ssum = v.x + v.y + v.z + v.w;
        float q = v.x*v.x + v.y*v.y + v.z*v.z + v.w*v.w;
        #pragma unroll
        for (int o = 16; o; o >>= 1) {
            ssum += __shfl_xor_sync(~0u, ssum, o);
            q += __shfl_xor_sync(~0u, q, o);
        }
        float mu = ssum * (1.f/128.f);
        float rs = rsqrtf(q * (1.f/128.f) - mu*mu + 1e-5f);
        const __half2* gp = (const __half2*)&g_gate[(t0 + m) * 128];
        float2 g0 = __half22float2(gp[lane*2]);
        float2 g1 = __half22float2(gp[lane*2 + 1]);
        rv[k][0] = ((v.x-mu)*rs*w4.x + b4.x) * g0.x;
        rv[k][1] = ((v.y-mu)*rs*w4.y + b4.y) * g0.y;
        rv[k][2] = ((v.z-mu)*rs*w4.z + b4.z) * g1.x;
        rv[k][3] = ((v.w-mu)*rs*w4.w + b4.w) * g1.y;
    }
    __syncthreads();   // everyone done reading s -> safe to alias

    #pragma unroll
    for (int k = 0; k < 8; k++) {
        int m = w + k * 8;
        int base = m * LDX + lane * 4;
        #pragma unroll
        for (int c = 0; c < 4; c++) {
            __nv_bfloat16 h = __float2bfloat16(rv[k][c]);
            yh[base + c] = h;
            yl[base + c] = __float2bfloat16(rv[k][c] - __bfloat162float(h));
        }
    }
    __syncthreads();

    // projection: 64 x 128 x 128 (bf16x3), weights from global (L1/L2-hot)
    const int mw = w & 1, nw2 = w >> 1, m0 = mw * 32, n0 = nw2 * 32;
    const __nv_bfloat16* Wh = g_wsh[5];
    const __nv_bfloat16* Wl = g_wsl[5];
    wmma::fragment<wmma::accumulator,16,16,16,float> acc[2][2];
    #pragma unroll
    for (int im = 0; im < 2; im++)
        #pragma unroll
        for (int in = 0; in < 2; in++) wmma::fill_fragment(acc[im][in], 0.f);

    for (int k0 = 0; k0 < 128; k0 += 16) {
        wmma::fragment<wmma::matrix_a,16,16,16,__nv_bfloat16,wmma::row_major> ah[2], al[2];
        wmma::fragment<wmma::matrix_b,16,16,16,__nv_bfloat16,wmma::col_major> bh[2], bl[2];
        #pragma unroll
        for (int im = 0; im < 2; im++) {
            wmma::load_matrix_sync(ah[im], yh + (m0+im*16)*LDX + k0, LDX);
            wmma::load_matrix_sync(al[im], yl + (m0+im*16)*LDX + k0, LDX);
        }
        #pragma unroll
        for (int in = 0; in < 2; in++) {
            wmma::load_matrix_sync(bh[in], Wh + (n0+in*16)*LDX + k0, LDX);
            wmma::load_matrix_sync(bl[in], Wl + (n0+in*16)*LDX + k0, LDX);
        }
        #pragma unroll
        for (int im = 0; im < 2; im++)
            #pragma unroll
            for (int in = 0; in < 2; in++) {
                wmma::mma_sync(acc[im][in], al[im], bh[in], acc[im][in]);
                wmma::mma_sync(acc[im][in], ah[im], bl[in], acc[im][in]);
                wmma::mma_sync(acc[im][in], ah[im], bh[in], acc[im][in]);
            }
    }
    #pragma unroll
    for (int im = 0; im < 2; im++)
        #pragma unroll
        for (int in = 0; in < 2; in++)
            wmma::store_matrix_sync(out + (t0 + m0 + im*16) * 128 + n0 + in*16,
                                    acc[im][in], 128, wmma::mem_row_major);
}

extern "C" void kernel_launch(void* const* d_in, const int* in_sizes, int n_in,
                              void* d_out, int out_size) {
    const float* x    = (const float*)d_in[0];
    const float* mask = (const float*)d_in[1];
    const float* nw   = (const float*)d_in[2];
    const float* nb   = (const float*)d_in[3];
    const float* wlft = (const float*)d_in[4];
    const float* wrgt = (const float*)d_in[5];
    const float* wlg  = (const float*)d_in[6];
    const float* wrg  = (const float*)d_in[7];
    const float* wog  = (const float*)d_in[8];
    const float* onw  = (const float*)d_in[9];
    const float* onb  = (const float*)d_in[10];
    const float* wout = (const float*)d_in[11];
    float* out = (float*)d_out;

    size_t smA = 2 * 128 * LDX * sizeof(__nv_bfloat16) + 69632 + 512;  // 139776
    size_t smB = 6 * 9216 * sizeof(__nv_bfloat16);                     // 110592
    size_t smC = 35840;
    cudaFuncSetAttribute(kA, cudaFuncAttributeMaxDynamicSharedMemorySize, (int)smA);
    cudaFuncSetAttribute(kB, cudaFuncAttributeMaxDynamicSharedMemorySize, (int)smB);
    cudaFuncSetAttribute(kC, cudaFuncAttributeMaxDynamicSharedMemorySize, (int)smC);

    kW<<<6, 256>>>(wlft, wrgt, wlg, wrg, wog, wout);
    kA<<<4608, 512, smA>>>(x, mask, nw, nb);
    kB<<<dim3(36, 128), 256, smB>>>();
    kC<<<9216, 256, smC>>>(onw, onb, out);
}

// round 17
// speedup vs baseline: 2.4864x; 1.0381x over previous
#include <cuda_runtime.h>
#include <cuda_bf16.h>
#include <cuda_fp16.h>
#include <mma.h>
#include <cstdint>

using namespace nvcuda;

static constexpr int NN = 768;
static constexpr size_t NTOK = (size_t)NN * NN;  // 589824

__device__ __align__(256) __nv_bfloat16 g_leftT[128 * 589824];   // [h][tok]
__device__ __align__(256) __nv_bfloat16 g_rightT[128 * 589824];  // [h][tok]
__device__ __align__(256) __half        g_gate[589824 * 128];    // [tok][h] fp16
__device__ __align__(256) __nv_bfloat16 g_outT[128 * 589824];    // [d][i*768+j]

#define LDX 136
// pre-split weights: 0=wl 1=wr 2=wlg 3=wrg 4=wog 5=wout
__device__ __align__(256) __nv_bfloat16 g_wsh[6][128 * LDX];
__device__ __align__(256) __nv_bfloat16 g_wsl[6][128 * LDX];

__device__ __forceinline__ float fsig(float z) { return 1.f / (1.f + __expf(-z)); }

__device__ __forceinline__ void cp16(void* smem, const void* g) {
    unsigned int s = (unsigned int)__cvta_generic_to_shared(smem);
    asm volatile("cp.async.cg.shared.global [%0], [%1], 16;\n" :: "r"(s), "l"(g));
}
#define CP_COMMIT() asm volatile("cp.async.commit_group;\n")
#define CP_WAIT(n)  asm volatile("cp.async.wait_group %0;\n" :: "n"(n))

// -------- Stage W: split 6 weight matrices into bf16 hi/lo ------------------
__global__ __launch_bounds__(256) void kW(
    const float* __restrict__ wl, const float* __restrict__ wr,
    const float* __restrict__ wlg, const float* __restrict__ wrg,
    const float* __restrict__ wog, const float* __restrict__ wout)
{
    const float* Ws[6] = { wl, wr, wlg, wrg, wog, wout };
    const float* W = Ws[blockIdx.x];
    for (int idx = threadIdx.x; idx < 128 * 128; idx += 256) {
        int n = idx >> 7, k = idx & 127;
        float v = W[idx];
        __nv_bfloat16 h = __float2bfloat16(v);
        g_wsh[blockIdx.x][n * LDX + k] = h;
        g_wsl[blockIdx.x][n * LDX + k] = __float2bfloat16(v - __bfloat162float(h));
    }
}

// -------- Stage A: LN + 5 projections (bf16x3) -------------------------------
// 64-token blocks, 256 threads, 2 blocks/SM (epilogue overlaps peer mainloop).
__global__ __launch_bounds__(256, 2) void kA(
    const float* __restrict__ x, const float* __restrict__ mask,
    const float* __restrict__ nw_, const float* __restrict__ nb_)
{
    extern __shared__ __align__(16) char smraw[];
    __nv_bfloat16* xh  = (__nv_bfloat16*)smraw;           // 64 x 136
    __nv_bfloat16* xl  = xh + 64 * LDX;                   // 64 x 136
    float* stage = (float*)(xl + 64 * LDX);               // 128 x 68 fp32
    float* msk   = stage + 128 * 68;                      // 64 floats

    const int tid = threadIdx.x, w = tid >> 5, lane = tid & 31;
    const size_t t0 = (size_t)blockIdx.x * 64;
    const int mw = w & 1, nwp = w >> 1;
    const int m0 = mw * 32, n0 = nwp * 32;

    // LayerNorm 64 tokens, split hi/lo into smem
    float4 nw4 = *(const float4*)&nw_[lane * 4];
    float4 nb4 = *(const float4*)&nb_[lane * 4];
    for (int m = w; m < 64; m += 8) {
        float4 v = *(const float4*)&x[(t0 + m) * 128 + lane * 4];
        float s = v.x + v.y + v.z + v.w;
        float q = v.x*v.x + v.y*v.y + v.z*v.z + v.w*v.w;
        #pragma unroll
        for (int o = 16; o; o >>= 1) {
            s += __shfl_xor_sync(~0u, s, o);
            q += __shfl_xor_sync(~0u, q, o);
        }
        float mu = s * (1.f/128.f);
        float rs = rsqrtf(q * (1.f/128.f) - mu*mu + 1e-5f);
        float y[4] = { (v.x-mu)*rs*nw4.x + nb4.x, (v.y-mu)*rs*nw4.y + nb4.y,
                       (v.z-mu)*rs*nw4.z + nb4.z, (v.w-mu)*rs*nw4.w + nb4.w };
        int base = m * LDX + lane * 4;
        #pragma unroll
        for (int c = 0; c < 4; c++) {
            __nv_bfloat16 h = __float2bfloat16(y[c]);
            xh[base + c] = h;
            xl[base + c] = __float2bfloat16(y[c] - __bfloat162float(h));
        }
    }
    if (tid < 64) msk[tid] = mask[t0 + tid];
    __syncthreads();

    const int PI[3] = { 0, 1, 4 }, GI[3] = { 2, 3, 0 };

    for (int p = 0; p < 3; p++) {
        const __nv_bfloat16* WPh = g_wsh[PI[p]];
        const __nv_bfloat16* WPl = g_wsl[PI[p]];
        const __nv_bfloat16* WGh = g_wsh[GI[p]];
        const __nv_bfloat16* WGl = g_wsl[GI[p]];

        wmma::fragment<wmma::accumulator,16,16,16,float> accP[2][2], accG[2][2];
        #pragma unroll
        for (int im = 0; im < 2; im++)
            #pragma unroll
            for (int in = 0; in < 2; in++) {
                wmma::fill_fragment(accP[im][in], 0.f);
                wmma::fill_fragment(accG[im][in], 0.f);
            }
        for (int k0 = 0; k0 < 128; k0 += 16) {
            wmma::fragment<wmma::matrix_a,16,16,16,__nv_bfloat16,wmma::row_major> ah[2], al[2];
            wmma::fragment<wmma::matrix_b,16,16,16,__nv_bfloat16,wmma::col_major> bh[2], bl[2], gh[2], gl[2];
            #pragma unroll
            for (int im = 0; im < 2; im++) {
                wmma::load_matrix_sync(ah[im], xh + (m0+im*16)*LDX + k0, LDX);
                wmma::load_matrix_sync(al[im], xl + (m0+im*16)*LDX + k0, LDX);
            }
            #pragma unroll
            for (int in = 0; in < 2; in++) {
                wmma::load_matrix_sync(bh[in], WPh + (n0+in*16)*LDX + k0, LDX);
                wmma::load_matrix_sync(bl[in], WPl + (n0+in*16)*LDX + k0, LDX);
                if (p < 2) {
                    wmma::load_matrix_sync(gh[in], WGh + (n0+in*16)*LDX + k0, LDX);
                    wmma::load_matrix_sync(gl[in], WGl + (n0+in*16)*LDX + k0, LDX);
                }
            }
            #pragma unroll
            for (int im = 0; im < 2; im++)
                #pragma unroll
                for (int in = 0; in < 2; in++) {
                    wmma::mma_sync(accP[im][in], al[im], bh[in], accP[im][in]);
                    wmma::mma_sync(accP[im][in], ah[im], bl[in], accP[im][in]);
                    wmma::mma_sync(accP[im][in], ah[im], bh[in], accP[im][in]);
                    if (p < 2) {
                        wmma::mma_sync(accG[im][in], al[im], gh[in], accG[im][in]);
                        wmma::mma_sync(accG[im][in], ah[im], gl[in], accG[im][in]);
                        wmma::mma_sync(accG[im][in], ah[im], gh[in], accG[im][in]);
                    }
                }
        }

        if (p < 2) {
            #pragma unroll
            for (int im = 0; im < 2; im++)
                #pragma unroll
                for (int in = 0; in < 2; in++)
                    #pragma unroll
                    for (int t = 0; t < 8; t++)
                        accP[im][in].x[t] *= fsig(accG[im][in].x[t]);
            __syncthreads();   // prior pass's stage readers done
            // stage transposed: stageT[n][m], ld 68 (mem_col_major)
            #pragma unroll
            for (int im = 0; im < 2; im++)
                #pragma unroll
                for (int in = 0; in < 2; in++)
                    wmma::store_matrix_sync(stage + (size_t)(n0+in*16)*68 + m0 + im*16,
                                            accP[im][in], 68, wmma::mem_col_major);
            __syncthreads();
            __nv_bfloat16* dst = (p == 0) ? g_leftT : g_rightT;
            for (int e = tid; e < 128 * 64; e += 256) {
                int n = e >> 6, m = e & 63;
                dst[(size_t)n * NTOK + t0 + m] =
                    __float2bfloat16(stage[n * 68 + m] * msk[m]);
            }
        } else {
            // out_gate: sigmoid -> fp16, staged for coalesced half2 stores
            #pragma unroll
            for (int im = 0; im < 2; im++)
                #pragma unroll
                for (int in = 0; in < 2; in++)
                    #pragma unroll
                    for (int t = 0; t < 8; t++)
                        accP[im][in].x[t] = fsig(accP[im][in].x[t]);
            __syncthreads();
            #pragma unroll
            for (int im = 0; im < 2; im++)
                #pragma unroll
                for (int in = 0; in < 2; in++)
                    wmma::store_matrix_sync(stage + (m0+im*16)*136 + n0 + in*16,
                                            accP[im][in], 136, wmma::mem_row_major);
            __syncthreads();
            for (int e = tid; e < 64 * 64; e += 256) {
                int m = e >> 6, hp = e & 63;
                __half2 hv = __halves2half2(__float2half(stage[m*136 + hp*2]),
                                            __float2half(stage[m*136 + hp*2 + 1]));
                *(__half2*)&g_gate[(t0 + m) * 128 + hp*2] = hv;
            }
        }
    }
}

// -------- Stage B: per-channel 768x768x768 bf16 GEMM, 3-stage cp.async ------
// Race-free single-sync pipeline; 2 blocks/SM for cross-block overlap.
__global__ __launch_bounds__(256, 2) void kB(void)
{
    extern __shared__ __align__(16) char sbuf[];   // 3 stages x (A,B) x 128x72 bf16
    __nv_bfloat16* sm = (__nv_bfloat16*)sbuf;      // stage s, mat t: sm + (s*2+t)*9216

    const int tid = threadIdx.x, w = tid >> 5, lane = tid & 31;
    const int d = blockIdx.y, ti = blockIdx.x % 6, tj = blockIdx.x / 6;
    const __nv_bfloat16* Lb = g_leftT  + (size_t)d * NTOK + (size_t)ti * 128 * NN;
    const __nv_bfloat16* Rb = g_rightT + (size_t)d * NTOK + (size_t)tj * 128 * NN;
    __nv_bfloat16* Ob = g_outT + (size_t)d * NTOK + (size_t)ti * 128 * NN + tj * 128;

    const int mw = w & 3, nw = w >> 2;
    wmma::fragment<wmma::accumulator,16,16,16,float> acc[2][4];
    #pragma unroll
    for (int im = 0; im < 2; im++)
        #pragma unroll
        for (int in = 0; in < 4; in++) wmma::fill_fragment(acc[im][in], 0.f);

    auto load_stage = [&](int s, int k0) {
        __nv_bfloat16* sA = sm + (s*2 + 0) * 9216;
        __nv_bfloat16* sB = sm + (s*2 + 1) * 9216;
        for (int i = tid; i < 1024; i += 256) {
            int r = i >> 3, c = (i & 7) * 8;
            cp16(&sA[r*72 + c], &Lb[(size_t)r*NN + k0 + c]);
            cp16(&sB[r*72 + c], &Rb[(size_t)r*NN + k0 + c]);
        }
    };

    load_stage(0, 0);   CP_COMMIT();
    load_stage(1, 64);  CP_COMMIT();
    const int NK = NN / 64;  // 12
    for (int i = 0; i < NK; i++) {
        if (i + 1 < NK) { CP_WAIT(1); } else { CP_WAIT(0); }
        __syncthreads();   // stage i visible; all warps done with iter i-1
        if (i + 2 < NK) { load_stage((i + 2) % 3, (i + 2) * 64); CP_COMMIT(); }
        const __nv_bfloat16* sA = sm + ((i % 3)*2 + 0) * 9216;
        const __nv_bfloat16* sB = sm + ((i % 3)*2 + 1) * 9216;
        #pragma unroll
        for (int ks = 0; ks < 64; ks += 16) {
            wmma::fragment<wmma::matrix_a,16,16,16,__nv_bfloat16,wmma::row_major> a[2];
            wmma::fragment<wmma::matrix_b,16,16,16,__nv_bfloat16,wmma::col_major> b[4];
            #pragma unroll
            for (int im = 0; im < 2; im++)
                wmma::load_matrix_sync(a[im], sA + (mw*32 + im*16)*72 + ks, 72);
            #pragma unroll
            for (int in = 0; in < 4; in++)
                wmma::load_matrix_sync(b[in], sB + (nw*64 + in*16)*72 + ks, 72);
            #pragma unroll
            for (int im = 0; im < 2; im++)
                #pragma unroll
                for (int in = 0; in < 4; in++)
                    wmma::mma_sync(acc[im][in], a[im], b[in], acc[im][in]);
        }
    }

    __syncthreads();
    float* ws = (float*)sbuf + w * (16 * 68);
    #pragma unroll
    for (int im = 0; im < 2; im++) {
        #pragma unroll
        for (int in = 0; in < 4; in++)
            wmma::store_matrix_sync(ws + in*16, acc[im][in], 68, wmma::mem_row_major);
        __syncwarp();
        int rbase = mw * 32 + im * 16;
        for (int e = lane; e < 16 * 64; e += 32) {
            int r = e >> 6, n = e & 63;
            Ob[(size_t)(rbase + r) * NN + nw*64 + n] = __float2bfloat16(ws[r*68 + n]);
        }
        __syncwarp();
    }
}

// -------- Stage C: channel LN + gate + final projection (bf16x3) ------------
// 64-token blocks, 256 threads; w_out fragments loaded straight from global.
__global__ __launch_bounds__(256) void kC(
    const float* __restrict__ onw, const float* __restrict__ onb,
    float* __restrict__ out)
{
    extern __shared__ __align__(16) char smraw[];
    float* s = (float*)smraw;                          // 64 x 140 fp32 (35840 B)
    __nv_bfloat16* yh = (__nv_bfloat16*)smraw;         // 64 x 136 (alias over s)
    __nv_bfloat16* yl = yh + 64 * LDX;

    const int tid = threadIdx.x, w = tid >> 5, lane = tid & 31;
    const size_t t0 = (size_t)blockIdx.x * 64;

    // gather transposed einsum output: s[m][d]
    for (int idx = tid; idx < 64 * 128; idx += 256) {
        int m = idx & 63, dch = idx >> 6;
        s[m * 140 + dch] = __bfloat162float(g_outT[(size_t)dch * NTOK + t0 + m]);
    }
    __syncthreads();

    // LN over channels + gate, results parked in registers
    float4 w4 = *(const float4*)&onw[lane * 4];
    float4 b4 = *(const float4*)&onb[lane * 4];
    float rv[8][4];
    #pragma unroll
    for (int k = 0; k < 8; k++) {
        int m = w + k * 8;
        float4 v = *(const float4*)&s[m * 140 + lane * 4];
        float ssum = v.x + v.y + v.z + v.w;
        float q = v.x*v.x + v.y*v.y + v.z*v.z + v.w*v.w;
        #pragma unroll
        for (int o = 16; o; o >>= 1) {
            ssum += __shfl_xor_sync(~0u, ssum, o);
            q += __shfl_xor_sync(~0u, q, o);
        }
        float mu = ssum * (1.f/128.f);
        float rs = rsqrtf(q * (1.f/128.f) - mu*mu + 1e-5f);
        const __half2* gp = (const __half2*)&g_gate[(t0 + m) * 128];
        float2 g0 = __half22float2(gp[lane*2]);
        float2 g1 = __half22float2(gp[lane*2 + 1]);
        rv[k][0] = ((v.x-mu)*rs*w4.x + b4.x) * g0.x;
        rv[k][1] = ((v.y-mu)*rs*w4.y + b4.y) * g0.y;
        rv[k][2] = ((v.z-mu)*rs*w4.z + b4.z) * g1.x;
        rv[k][3] = ((v.w-mu)*rs*w4.w + b4.w) * g1.y;
    }
    __syncthreads();   // everyone done reading s -> safe to alias

    #pragma unroll
    for (int k = 0; k < 8; k++) {
        int m = w + k * 8;
        int base = m * LDX + lane * 4;
        #pragma unroll
        for (int c = 0; c < 4; c++) {
            __nv_bfloat16 h = __float2bfloat16(rv[k][c]);
            yh[base + c] = h;
            yl[base + c] = __float2bfloat16(rv[k][c] - __bfloat162float(h));
        }
    }
    __syncthreads();

    // projection: 64 x 128 x 128 (bf16x3), weights from global (L1/L2-hot)
    const int mw = w & 1, nw2 = w >> 1, m0 = mw * 32, n0 = nw2 * 32;
    const __nv_bfloat16* Wh = g_wsh[5];
    const __nv_bfloat16* Wl = g_wsl[5];
    wmma::fragment<wmma::accumulator,16,16,16,float> acc[2][2];
    #pragma unroll
    for (int im = 0; im < 2; im++)
        #pragma unroll
        for (int in = 0; in < 2; in++) wmma::fill_fragment(acc[im][in], 0.f);

    for (int k0 = 0; k0 < 128; k0 += 16) {
        wmma::fragment<wmma::matrix_a,16,16,16,__nv_bfloat16,wmma::row_major> ah[2], al[2];
        wmma::fragment<wmma::matrix_b,16,16,16,__nv_bfloat16,wmma::col_major> bh[2], bl[2];
        #pragma unroll
        for (int im = 0; im < 2; im++) {
            wmma::load_matrix_sync(ah[im], yh + (m0+im*16)*LDX + k0, LDX);
            wmma::load_matrix_sync(al[im], yl + (m0+im*16)*LDX + k0, LDX);
        }
        #pragma unroll
        for (int in = 0; in < 2; in++) {
            wmma::load_matrix_sync(bh[in], Wh + (n0+in*16)*LDX + k0, LDX);
            wmma::load_matrix_sync(bl[in], Wl + (n0+in*16)*LDX + k0, LDX);
        }
        #pragma unroll
        for (int im = 0; im < 2; im++)
            #pragma unroll
            for (int in = 0; in < 2; in++) {
                wmma::mma_sync(acc[im][in], al[im], bh[in], acc[im][in]);
                wmma::mma_sync(acc[im][in], ah[im], bl[in], acc[im][in]);
                wmma::mma_sync(acc[im][in], ah[im], bh[in], acc[im][in]);
            }
    }
    #pragma unroll
    for (int im = 0; im < 2; im++)
        #pragma unroll
        for (int in = 0; in < 2; in++)
            wmma::store_matrix_sync(out + (t0 + m0 + im*16) * 128 + n0 + in*16,
                                    acc[im][in], 128, wmma::mem_row_major);
}

extern "C" void kernel_launch(void* const* d_in, const int* in_sizes, int n_in,
                              void* d_out, int out_size) {
    const float* x    = (const float*)d_in[0];
    const float* mask = (const float*)d_in[1];
    const float* nw   = (const float*)d_in[2];
    const float* nb   = (const float*)d_in[3];
    const float* wlft = (const float*)d_in[4];
    const float* wrgt = (const float*)d_in[5];
    const float* wlg  = (const float*)d_in[6];
    const float* wrg  = (const float*)d_in[7];
    const float* wog  = (const float*)d_in[8];
    const float* onw  = (const float*)d_in[9];
    const float* onb  = (const float*)d_in[10];
    const float* wout = (const float*)d_in[11];
    float* out = (float*)d_out;

    size_t smA = 2 * 64 * LDX * sizeof(__nv_bfloat16) + 128 * 68 * sizeof(float) + 512;  // ~70 KB
    size_t smB = 6 * 9216 * sizeof(__nv_bfloat16);                                       // 110592
    size_t smC = 35840;
    cudaFuncSetAttribute(kA, cudaFuncAttributeMaxDynamicSharedMemorySize, (int)smA);
    cudaFuncSetAttribute(kB, cudaFuncAttributeMaxDynamicSharedMemorySize, (int)smB);
    cudaFuncSetAttribute(kC, cudaFuncAttributeMaxDynamicSharedMemorySize, (int)smC);

    kW<<<6, 256>>>(wlft, wrgt, wlg, wrg, wog, wout);
    kA<<<9216, 256, smA>>>(x, mask, nw, nb);
    kB<<<dim3(36, 128), 256, smB>>>();
    kC<<<9216, 256, smC>>>(onw, onb, out);
}